// round 15
// baseline (speedup 1.0000x reference)
#include <cuda_runtime.h>
#include <cuda_bf16.h>
#include <cstdint>

// Problem constants
#define NROWS 131072
#define KMU   256
#define DDIM  128
#define MT    64                  // rows per CTA tile
#define NTILES (NROWS / MT)       // 2048
#define NCTAS  304                // 2 per SM on 152-SM GB300
#define THREADS 512               // 16 warps = 2 row-groups x 8 col-groups

// padded bf16 smem row: 128 bf16 + 8 pad = 272 bytes (conflict-free ldmatrix)
#define RSTRIDE 272
#define BUFSZ   (MT * RSTRIDE)    // 17408 per x buffer

// dynamic smem byte offsets (per CTA): total 113664 -> 2 CTAs = 227328 <= 228KB
#define SW    0                       // W tile 256 x 272 = 69632 (permanent)
#define SBUF  69632                   // 2 x 17408 = 34816 -> 104448
#define SPART 104448                  // 64 rows x 36 floats = 9216 -> 113664
                                      // adj_s (1KB) overlays SPART during prologue
                                      // red_s (64B) overlays SPART after last merge
#define SMEM_TOTAL 113664

#define L2E 1.4426950408889634f
#define LN2 0.69314718055994531f
#define CSHIFT 32.0f               // centering shift; >70 binades of fp32 margin

__device__ float g_partials[NCTAS];
__device__ unsigned int g_count = 0;

__device__ __forceinline__ uint32_t smem_u32(const void* p) {
    uint32_t a;
    asm("{ .reg .u64 t; cvta.to.shared.u64 t, %1; cvt.u32.u64 %0, t; }" : "=r"(a) : "l"(p));
    return a;
}

__device__ __forceinline__ void ldm_x4(uint32_t addr, uint32_t& r0, uint32_t& r1,
                                       uint32_t& r2, uint32_t& r3) {
    asm volatile("ldmatrix.sync.aligned.m8n8.x4.shared.b16 {%0,%1,%2,%3}, [%4];"
                 : "=r"(r0), "=r"(r1), "=r"(r2), "=r"(r3) : "r"(addr));
}

__device__ __forceinline__ void mma16816(float* d, const uint32_t* a, const uint32_t* b) {
    asm volatile(
        "mma.sync.aligned.m16n8k16.row.col.f32.bf16.bf16.f32 "
        "{%0,%1,%2,%3}, {%4,%5,%6,%7}, {%8,%9}, {%0,%1,%2,%3};"
        : "+f"(d[0]), "+f"(d[1]), "+f"(d[2]), "+f"(d[3])
        : "r"(a[0]), "r"(a[1]), "r"(a[2]), "r"(a[3]), "r"(b[0]), "r"(b[1]));
}

__device__ __forceinline__ float ex2f(float x) {
    float y; asm("ex2.approx.ftz.f32 %0, %1;" : "=f"(y) : "f"(x)); return y;
}
__device__ __forceinline__ float lg2f(float x) {
    float y; asm("lg2.approx.ftz.f32 %0, %1;" : "=f"(y) : "f"(x)); return y;
}

__global__ void __launch_bounds__(THREADS, 2)
gmm_lse_kernel(const float* __restrict__ x, const float* __restrict__ mu,
               const float* __restrict__ prec, float* __restrict__ out) {
    extern __shared__ char smem[];
    const uint32_t sb = smem_u32(smem);
    const int tid = threadIdx.x;
    const int w = tid >> 5;           // 0..15
    const int l = tid & 31;
    const int m = l >> 3, r = l & 7;
    const int rg = w >> 3;            // row-group 0..1 (32 rows each)
    const int cg = w & 7;             // col-group 0..7 (32 cols each)

    float* adj_s = (float*)(smem + SPART);        // prologue-only overlay
    __shared__ unsigned int last_flag;

    // per-lane precision slice (cols 4l..4l+3)
    const float4 pc = ((const float4*)prec)[l];

    // ---- prologue: stage W = prec*mu as bf16 at SW (256 x 272), adj[k] ----
    {
        const float4* mr = (const float4*)(mu + (long)(w * 16) * DDIM);
        #pragma unroll 4
        for (int i = 0; i < 16; i++) {
            const int krow = w * 16 + i;
            float4 f = mr[i * 32 + l];
            float wx = pc.x * f.x, wy = pc.y * f.y, wz = pc.z * f.z, ww = pc.w * f.w;
            float s = wx * f.x;
            s = fmaf(wy, f.y, s);
            s = fmaf(wz, f.z, s);
            s = fmaf(ww, f.w, s);
            #pragma unroll
            for (int o = 16; o; o >>= 1) s += __shfl_xor_sync(0xFFFFFFFFu, s, o);
            __nv_bfloat162 lo = __floats2bfloat162_rn(wx, wy);
            __nv_bfloat162 hi = __floats2bfloat162_rn(wz, ww);
            uint2 v;
            v.x = *(uint32_t*)&lo;
            v.y = *(uint32_t*)&hi;
            *(uint2*)(smem + SW + krow * RSTRIDE + l * 8) = v;
            if (l == 0) adj_s[krow] = -0.5f * s * L2E;
        }
    }
    __syncthreads();

    // adj (+CSHIFT) for this lane's 8 columns (read BEFORE SPART is reused)
    float av[8];
    #pragma unroll
    for (int t = 0; t < 4; t++) {
        const int col = cg * 32 + 8 * t + 2 * (l & 3);
        av[2 * t]     = adj_s[col]     + CSHIFT;
        av[2 * t + 1] = adj_s[col + 1] + CSHIFT;
    }
    __syncthreads();   // everyone done with adj_s; SPART free for partials

    float acc_thr = 0.f;
    float xsq_acc = 0.f;

    // ---- stage first tile into buf0: warp w loads rows w*4..w*4+3 ----
    {
        const int tile0 = blockIdx.x;
        const float4* xr = (const float4*)(x + (long)(tile0 * MT + w * 4) * DDIM);
        #pragma unroll
        for (int i = 0; i < 4; i++) {
            float4 f = xr[i * 32 + l];
            xsq_acc = fmaf(pc.x * f.x, f.x, xsq_acc);
            xsq_acc = fmaf(pc.y * f.y, f.y, xsq_acc);
            xsq_acc = fmaf(pc.z * f.z, f.z, xsq_acc);
            xsq_acc = fmaf(pc.w * f.w, f.w, xsq_acc);
            __nv_bfloat162 lo = __floats2bfloat162_rn(f.x, f.y);
            __nv_bfloat162 hi = __floats2bfloat162_rn(f.z, f.w);
            uint2 v;
            v.x = *(uint32_t*)&lo;
            v.y = *(uint32_t*)&hi;
            *(uint2*)(smem + SBUF + (w * 4 + i) * RSTRIDE + l * 8) = v;
        }
    }
    __syncthreads();

    int par = 0;
    for (int tile = blockIdx.x; tile < NTILES; tile += gridDim.x, par ^= 1) {
        const uint32_t cur = sb + SBUF + par * BUFSZ;

        // ---- stage NEXT tile into the other buffer ----
        const int nxt = tile + gridDim.x;
        if (nxt < NTILES) {
            const float4* xr = (const float4*)(x + (long)(nxt * MT + w * 4) * DDIM);
            #pragma unroll
            for (int i = 0; i < 4; i++) {
                float4 f = xr[i * 32 + l];
                xsq_acc = fmaf(pc.x * f.x, f.x, xsq_acc);
                xsq_acc = fmaf(pc.y * f.y, f.y, xsq_acc);
                xsq_acc = fmaf(pc.z * f.z, f.z, xsq_acc);
                xsq_acc = fmaf(pc.w * f.w, f.w, xsq_acc);
                __nv_bfloat162 lo = __floats2bfloat162_rn(f.x, f.y);
                __nv_bfloat162 hi = __floats2bfloat162_rn(f.z, f.w);
                uint2 v;
                v.x = *(uint32_t*)&lo;
                v.y = *(uint32_t*)&hi;
                *(uint2*)(smem + SBUF + (par ^ 1) * BUFSZ + (w * 4 + i) * RSTRIDE + l * 8) = v;
            }
        }

        // ---- compute: warp = rows [rg*32, rg*32+32) x cols [cg*32, cg*32+32) ----
        #pragma unroll
        for (int mt = 0; mt < 2; mt++) {
            float acc[4][4] = {};
            uint32_t a0[4], a1[4];
            const uint32_t rowad = cur
                + (rg * 32 + mt * 16 + ((m & 1) << 3) + r) * RSTRIDE
                + (((m >> 1) << 3)) * 2;
            const uint32_t bad = sb + SW
                + (cg * 32 + ((m >> 1) << 3) + r) * RSTRIDE
                + (((m & 1) << 3)) * 2;
            ldm_x4(rowad, a0[0], a0[1], a0[2], a0[3]);
            #pragma unroll
            for (int ks = 0; ks < 8; ks++) {
                uint32_t* ac = (ks & 1) ? a1 : a0;
                uint32_t* an = (ks & 1) ? a0 : a1;
                if (ks < 7)
                    ldm_x4(rowad + ((ks + 1) << 5), an[0], an[1], an[2], an[3]);
                // B fragments for this ks, streamed from permanent W smem
                uint32_t b0[4], b1[4];
                ldm_x4(bad + (ks << 5),                  b0[0], b0[1], b0[2], b0[3]);
                ldm_x4(bad + (ks << 5) + 16 * RSTRIDE,   b1[0], b1[1], b1[2], b1[3]);
                mma16816(acc[0], ac, &b0[0]);
                mma16816(acc[1], ac, &b0[2]);
                mma16816(acc[2], ac, &b1[0]);
                mma16816(acc[3], ac, &b1[2]);
            }
            // per-lane 8-col partial sum of exp2(v), no max, no shfl
            #pragma unroll
            for (int sub = 0; sub < 2; sub++) {
                float s01 = ex2f(fmaf(acc[0][sub * 2],     L2E, av[0]))
                          + ex2f(fmaf(acc[0][sub * 2 + 1], L2E, av[1]));
                float s23 = ex2f(fmaf(acc[1][sub * 2],     L2E, av[2]))
                          + ex2f(fmaf(acc[1][sub * 2 + 1], L2E, av[3]));
                float s45 = ex2f(fmaf(acc[2][sub * 2],     L2E, av[4]))
                          + ex2f(fmaf(acc[2][sub * 2 + 1], L2E, av[5]));
                float s67 = ex2f(fmaf(acc[3][sub * 2],     L2E, av[6]))
                          + ex2f(fmaf(acc[3][sub * 2 + 1], L2E, av[7]));
                const float s = (s01 + s23) + (s45 + s67);
                const int row = rg * 32 + mt * 16 + sub * 8 + (l >> 2);
                // slot = cg*4 + (l&3); stride 36 floats -> conflict-free
                ((float*)(smem + SPART))[row * 36 + cg * 4 + (l & 3)] = s;
            }
        }
        __syncthreads();

        // ---- merge: deterministic fp32 sum of 32 partials + one lg2 per row ----
        if (tid < MT) {
            const float4* pr = (const float4*)(smem + SPART + tid * 144);
            float s = 0.f;
            #pragma unroll
            for (int j = 0; j < 8; j++) {
                float4 f = pr[j];
                s += ((f.x + f.y) + (f.z + f.w));
            }
            acc_thr += LN2 * (lg2f(s) - CSHIFT);
        }
        __syncthreads();
    }

    // fold thread-local xsq (additive pass-through of logsumexp)
    acc_thr -= 0.5f * xsq_acc;

    // ---- deterministic block reduction (red_s overlays SPART; merges all done) ----
    float* red_s = (float*)(smem + SPART);
    float a = acc_thr;
    #pragma unroll
    for (int o = 16; o; o >>= 1) a += __shfl_xor_sync(0xFFFFFFFFu, a, o);
    __syncthreads();
    if (l == 0) red_s[w] = a;
    __syncthreads();
    if (tid == 0) {
        float t = 0.f;
        #pragma unroll
        for (int i = 0; i < 16; i++) t += red_s[i];
        g_partials[blockIdx.x] = t;
        __threadfence();
        unsigned int c = atomicAdd(&g_count, 1u);
        last_flag = (c == (unsigned)(gridDim.x - 1)) ? 1u : 0u;
    }
    __syncthreads();

    // ---- last CTA: deterministic final reduction (fixed lane->index map) ----
    if (last_flag && w == 0) {
        float s = 0.f;
        #pragma unroll
        for (int i = l; i < NCTAS; i += 32) s += __ldcg(&g_partials[i]);
        #pragma unroll
        for (int o = 16; o; o >>= 1) s += __shfl_xor_sync(0xFFFFFFFFu, s, o);
        if (l == 0) {
            out[0] = -s;
            g_count = 0;          // reset for next graph replay
            __threadfence();
        }
    }
}

extern "C" void kernel_launch(void* const* d_in, const int* in_sizes, int n_in,
                              void* d_out, int out_size) {
    const float* x    = (const float*)d_in[0];
    const float* mu   = (const float*)d_in[1];
    const float* prec = (const float*)d_in[2];
    float* out = (float*)d_out;

    cudaFuncSetAttribute(gmm_lse_kernel, cudaFuncAttributeMaxDynamicSharedMemorySize, SMEM_TOTAL);
    gmm_lse_kernel<<<NCTAS, THREADS, SMEM_TOTAL>>>(x, mu, prec, out);
}

// round 16
// speedup vs baseline: 1.1803x; 1.1803x over previous
#include <cuda_runtime.h>
#include <cuda_fp16.h>
#include <cstdint>

// Problem constants
#define NROWS 131072
#define KMU   256
#define DDIM  128
#define MT    128                 // rows per CTA tile
#define NTILES (NROWS / MT)       // 1024
#define NCTAS  304                // 2 per SM on 152-SM GB300
#define THREADS 256               // 8 warps; warp owns 32 of 256 columns

// padded fp16 smem row: 128 half + 8 pad = 272 bytes (conflict-free ldmatrix)
#define RSTRIDE 272
#define BUFSZ   (MT * RSTRIDE)    // 34816 per x buffer

// dynamic smem byte offsets
// prologue: W tile (256 x 272 = 69632) exactly overlays the two x buffers
#define SBUF  0                       // 2 x 34816 = 69632
#define SADJ  69632                   // 256 floats -> 70656
#define SPART 70656                   // 128 rows x 36 floats (bank-conflict-free) -> 89088
#define SRED  89088                   // 8 floats -> 89120
#define SMEM_TOTAL 89120

#define L2E 1.4426950408889634f
#define LN2 0.69314718055994531f
#define CSHIFT 32.0f               // centering shift; >70 binades of fp32 margin

__device__ float g_partials[NCTAS];
__device__ unsigned int g_count = 0;

__device__ __forceinline__ uint32_t smem_u32(const void* p) {
    uint32_t a;
    asm("{ .reg .u64 t; cvta.to.shared.u64 t, %1; cvt.u32.u64 %0, t; }" : "=r"(a) : "l"(p));
    return a;
}

__device__ __forceinline__ void ldm_x4(uint32_t addr, uint32_t& r0, uint32_t& r1,
                                       uint32_t& r2, uint32_t& r3) {
    asm volatile("ldmatrix.sync.aligned.m8n8.x4.shared.b16 {%0,%1,%2,%3}, [%4];"
                 : "=r"(r0), "=r"(r1), "=r"(r2), "=r"(r3) : "r"(addr));
}

// f16 x f16 -> f16-accum MMA (2x rate vs f32-accum on mma.sync)
__device__ __forceinline__ void mma16816_h(uint32_t* d, const uint32_t* a, const uint32_t* b) {
    asm volatile(
        "mma.sync.aligned.m16n8k16.row.col.f16.f16.f16.f16 "
        "{%0,%1}, {%2,%3,%4,%5}, {%6,%7}, {%0,%1};"
        : "+r"(d[0]), "+r"(d[1])
        : "r"(a[0]), "r"(a[1]), "r"(a[2]), "r"(a[3]), "r"(b[0]), "r"(b[1]));
}

__device__ __forceinline__ float ex2f(float x) {
    float y; asm("ex2.approx.ftz.f32 %0, %1;" : "=f"(y) : "f"(x)); return y;
}
__device__ __forceinline__ float lg2f(float x) {
    float y; asm("lg2.approx.ftz.f32 %0, %1;" : "=f"(y) : "f"(x)); return y;
}

__global__ void __launch_bounds__(THREADS, 2)
gmm_lse_kernel(const float* __restrict__ x, const float* __restrict__ mu,
               const float* __restrict__ prec, float* __restrict__ out) {
    extern __shared__ char smem[];
    const uint32_t sb = smem_u32(smem);
    const int tid = threadIdx.x;
    const int w = tid >> 5;
    const int l = tid & 31;
    const int m = l >> 3, r = l & 7;

    float* adj_s  = (float*)(smem + SADJ);
    float* red_s  = (float*)(smem + SRED);
    __shared__ unsigned int last_flag;

    // per-lane precision slice (cols 4l..4l+3)
    const float4 pc = ((const float4*)prec)[l];

    // ---- prologue: stage W = prec*mu as fp16 at offset 0 (256 x 272), adj[k] ----
    {
        const float4* mr = (const float4*)(mu + (long)(w * 32) * DDIM);
        #pragma unroll 4
        for (int i = 0; i < 32; i++) {
            const int krow = w * 32 + i;
            float4 f = mr[i * 32 + l];
            float wx = pc.x * f.x, wy = pc.y * f.y, wz = pc.z * f.z, ww = pc.w * f.w;
            float s = wx * f.x;
            s = fmaf(wy, f.y, s);
            s = fmaf(wz, f.z, s);
            s = fmaf(ww, f.w, s);
            #pragma unroll
            for (int o = 16; o; o >>= 1) s += __shfl_xor_sync(0xFFFFFFFFu, s, o);
            __half2 lo = __floats2half2_rn(wx, wy);
            __half2 hi = __floats2half2_rn(wz, ww);
            uint2 v;
            v.x = *(uint32_t*)&lo;
            v.y = *(uint32_t*)&hi;
            *(uint2*)(smem + krow * RSTRIDE + l * 8) = v;
            if (l == 0) adj_s[krow] = -0.5f * s * L2E;
        }
    }
    __syncthreads();

    // ---- register-resident B fragments: warp w owns cols [32w, 32w+32) ----
    uint32_t B[8][2][4];   // 64 regs
    #pragma unroll
    for (int ks = 0; ks < 8; ks++) {
        #pragma unroll
        for (int tp = 0; tp < 2; tp++) {
            uint32_t addr = sb
                + (w * 32 + tp * 16 + ((m >> 1) << 3) + r) * RSTRIDE
                + ((ks << 4) + ((m & 1) << 3)) * 2;
            ldm_x4(addr, B[ks][tp][0], B[ks][tp][1], B[ks][tp][2], B[ks][tp][3]);
        }
    }
    // adj (+CSHIFT) for this lane's 8 columns, fp32
    float av[8];
    #pragma unroll
    for (int t = 0; t < 4; t++) {
        const int col = w * 32 + 8 * t + 2 * (l & 3);
        av[2 * t]     = adj_s[col]     + CSHIFT;
        av[2 * t + 1] = adj_s[col + 1] + CSHIFT;
    }
    __syncthreads();   // W region dead; x double-buffer lives at SBUF

    float acc_thr = 0.f;
    float xsq_acc = 0.f;

    // ---- stage first tile into buf0: warp w loads rows w*16..w*16+15 ----
    {
        const int tile0 = blockIdx.x;
        const float4* xr = (const float4*)(x + (long)(tile0 * MT + w * 16) * DDIM);
        #pragma unroll 8
        for (int i = 0; i < 16; i++) {
            float4 f = xr[i * 32 + l];
            xsq_acc = fmaf(pc.x * f.x, f.x, xsq_acc);
            xsq_acc = fmaf(pc.y * f.y, f.y, xsq_acc);
            xsq_acc = fmaf(pc.z * f.z, f.z, xsq_acc);
            xsq_acc = fmaf(pc.w * f.w, f.w, xsq_acc);
            __half2 lo = __floats2half2_rn(f.x, f.y);
            __half2 hi = __floats2half2_rn(f.z, f.w);
            uint2 v;
            v.x = *(uint32_t*)&lo;
            v.y = *(uint32_t*)&hi;
            *(uint2*)(smem + SBUF + (w * 16 + i) * RSTRIDE + l * 8) = v;
        }
    }
    __syncthreads();

    int par = 0;
    for (int tile = blockIdx.x; tile < NTILES; tile += gridDim.x, par ^= 1) {
        const uint32_t cur = sb + SBUF + par * BUFSZ;

        // ---- stage NEXT tile into the other buffer ----
        const int nxt = tile + gridDim.x;
        if (nxt < NTILES) {
            const float4* xr = (const float4*)(x + (long)(nxt * MT + w * 16) * DDIM);
            #pragma unroll 8
            for (int i = 0; i < 16; i++) {
                float4 f = xr[i * 32 + l];
                xsq_acc = fmaf(pc.x * f.x, f.x, xsq_acc);
                xsq_acc = fmaf(pc.y * f.y, f.y, xsq_acc);
                xsq_acc = fmaf(pc.z * f.z, f.z, xsq_acc);
                xsq_acc = fmaf(pc.w * f.w, f.w, xsq_acc);
                __half2 lo = __floats2half2_rn(f.x, f.y);
                __half2 hi = __floats2half2_rn(f.z, f.w);
                uint2 v;
                v.x = *(uint32_t*)&lo;
                v.y = *(uint32_t*)&hi;
                *(uint2*)(smem + SBUF + (par ^ 1) * BUFSZ + (w * 16 + i) * RSTRIDE + l * 8) = v;
            }
        }

        // ---- compute: warp w = all 128 rows x its 32 cols; fp16-accum MMA ----
        #pragma unroll 1
        for (int mt = 0; mt < 8; mt++) {
            uint32_t acc[4][2] = {};   // half2 accumulators: {c0,c1},{c2,c3}
            uint32_t a0[4], a1[4];
            const uint32_t rowad = cur + (mt * 16 + ((m & 1) << 3) + r) * RSTRIDE
                                 + (((m >> 1) << 3)) * 2;
            ldm_x4(rowad, a0[0], a0[1], a0[2], a0[3]);
            #pragma unroll
            for (int ks = 0; ks < 8; ks++) {
                uint32_t* ac = (ks & 1) ? a1 : a0;
                uint32_t* an = (ks & 1) ? a0 : a1;
                if (ks < 7)
                    ldm_x4(rowad + ((ks + 1) << 5), an[0], an[1], an[2], an[3]);
                #pragma unroll
                for (int t = 0; t < 4; t++)
                    mma16816_h(acc[t], ac, &B[ks][t >> 1][(t & 1) * 2]);
            }
            // per-lane 8-col partial sum of exp2(v): unpack half2 -> fp32, no max
            #pragma unroll
            for (int sub = 0; sub < 2; sub++) {
                float2 f0 = __half22float2(*(__half2*)&acc[0][sub]);
                float2 f1 = __half22float2(*(__half2*)&acc[1][sub]);
                float2 f2 = __half22float2(*(__half2*)&acc[2][sub]);
                float2 f3 = __half22float2(*(__half2*)&acc[3][sub]);
                float s01 = ex2f(fmaf(f0.x, L2E, av[0])) + ex2f(fmaf(f0.y, L2E, av[1]));
                float s23 = ex2f(fmaf(f1.x, L2E, av[2])) + ex2f(fmaf(f1.y, L2E, av[3]));
                float s45 = ex2f(fmaf(f2.x, L2E, av[4])) + ex2f(fmaf(f2.y, L2E, av[5]));
                float s67 = ex2f(fmaf(f3.x, L2E, av[6])) + ex2f(fmaf(f3.y, L2E, av[7]));
                const float s = (s01 + s23) + (s45 + s67);
                const int row = mt * 16 + sub * 8 + (l >> 2);
                // slot = w*4 + (l&3); stride 36 floats -> conflict-free
                ((float*)(smem + SPART))[row * 36 + w * 4 + (l & 3)] = s;
            }
        }
        __syncthreads();

        // ---- merge: pure deterministic fp32 sum of 32 partials + one lg2 per row ----
        if (tid < MT) {
            const float4* pr = (const float4*)(smem + SPART + tid * 144);
            float s = 0.f;
            #pragma unroll
            for (int j = 0; j < 8; j++) {
                float4 f = pr[j];
                s += ((f.x + f.y) + (f.z + f.w));
            }
            acc_thr += LN2 * (lg2f(s) - CSHIFT);
        }
        __syncthreads();
    }

    // fold thread-local xsq (additive pass-through of logsumexp)
    acc_thr -= 0.5f * xsq_acc;

    // ---- deterministic block reduction ----
    float a = acc_thr;
    #pragma unroll
    for (int o = 16; o; o >>= 1) a += __shfl_xor_sync(0xFFFFFFFFu, a, o);
    if (l == 0) red_s[w] = a;
    __syncthreads();
    if (tid == 0) {
        float t = 0.f;
        #pragma unroll
        for (int i = 0; i < 8; i++) t += red_s[i];
        g_partials[blockIdx.x] = t;
        __threadfence();
        unsigned int c = atomicAdd(&g_count, 1u);
        last_flag = (c == (unsigned)(gridDim.x - 1)) ? 1u : 0u;
    }
    __syncthreads();

    // ---- last CTA: deterministic final reduction (fixed lane->index map) ----
    if (last_flag && w == 0) {
        float s = 0.f;
        #pragma unroll
        for (int i = l; i < NCTAS; i += 32) s += __ldcg(&g_partials[i]);
        #pragma unroll
        for (int o = 16; o; o >>= 1) s += __shfl_xor_sync(0xFFFFFFFFu, s, o);
        if (l == 0) {
            out[0] = -s;
            g_count = 0;          // reset for next graph replay
            __threadfence();
        }
    }
}

extern "C" void kernel_launch(void* const* d_in, const int* in_sizes, int n_in,
                              void* d_out, int out_size) {
    const float* x    = (const float*)d_in[0];
    const float* mu   = (const float*)d_in[1];
    const float* prec = (const float*)d_in[2];
    float* out = (float*)d_out;

    cudaFuncSetAttribute(gmm_lse_kernel, cudaFuncAttributeMaxDynamicSharedMemorySize, SMEM_TOTAL);
    gmm_lse_kernel<<<NCTAS, THREADS, SMEM_TOTAL>>>(x, mu, prec, out);
}

// round 17
// speedup vs baseline: 1.1813x; 1.0009x over previous
#include <cuda_runtime.h>
#include <cuda_fp16.h>
#include <cstdint>

// Problem constants
#define NROWS 131072
#define KMU   256
#define DDIM  128
#define MT    128                 // rows per CTA tile
#define NTILES (NROWS / MT)       // 1024
#define NCTAS  304                // 2 per SM on 152-SM GB300
#define THREADS 256               // 8 warps; warp owns 32 of 256 columns

// padded fp16 smem row: 128 half + 8 pad = 272 bytes (conflict-free ldmatrix)
#define RSTRIDE 272
#define BUFSZ   (MT * RSTRIDE)    // 34816 per x buffer

// dynamic smem byte offsets
// prologue: W tile (256 x 272 = 69632) exactly overlays the two x buffers
#define SBUF  0                       // 2 x 34816 = 69632
#define SADJ  69632                   // 256 floats -> 70656
#define SPART 70656                   // 128 rows x 36 floats (bank-conflict-free) -> 89088
#define SRED  89088                   // 8 floats -> 89120
#define SMEM_TOTAL 89120

#define L2E 1.4426950408889634f
#define LN2 0.69314718055994531f
#define CSHIFT 32.0f               // centering shift; >70 binades of fp32 margin

__device__ float g_partials[NCTAS];
__device__ unsigned int g_count = 0;

__device__ __forceinline__ uint32_t smem_u32(const void* p) {
    uint32_t a;
    asm("{ .reg .u64 t; cvta.to.shared.u64 t, %1; cvt.u32.u64 %0, t; }" : "=r"(a) : "l"(p));
    return a;
}

__device__ __forceinline__ void ldm_x4(uint32_t addr, uint32_t& r0, uint32_t& r1,
                                       uint32_t& r2, uint32_t& r3) {
    asm volatile("ldmatrix.sync.aligned.m8n8.x4.shared.b16 {%0,%1,%2,%3}, [%4];"
                 : "=r"(r0), "=r"(r1), "=r"(r2), "=r"(r3) : "r"(addr));
}

// f16 x f16 -> f16-accum MMA (fewer acc regs; same tensor rate on this die)
__device__ __forceinline__ void mma16816_h(uint32_t* d, const uint32_t* a, const uint32_t* b) {
    asm volatile(
        "mma.sync.aligned.m16n8k16.row.col.f16.f16.f16.f16 "
        "{%0,%1}, {%2,%3,%4,%5}, {%6,%7}, {%0,%1};"
        : "+r"(d[0]), "+r"(d[1])
        : "r"(a[0]), "r"(a[1]), "r"(a[2]), "r"(a[3]), "r"(b[0]), "r"(b[1]));
}

__device__ __forceinline__ float ex2f(float x) {
    float y; asm("ex2.approx.ftz.f32 %0, %1;" : "=f"(y) : "f"(x)); return y;
}
__device__ __forceinline__ float lg2f(float x) {
    float y; asm("lg2.approx.ftz.f32 %0, %1;" : "=f"(y) : "f"(x)); return y;
}

__global__ void __launch_bounds__(THREADS, 2)
gmm_lse_kernel(const float* __restrict__ x, const float* __restrict__ mu,
               const float* __restrict__ prec, float* __restrict__ out) {
    extern __shared__ char smem[];
    const uint32_t sb = smem_u32(smem);
    const int tid = threadIdx.x;
    const int w = tid >> 5;
    const int l = tid & 31;
    const int m = l >> 3, r = l & 7;

    float* adj_s  = (float*)(smem + SADJ);
    float* red_s  = (float*)(smem + SRED);
    __shared__ unsigned int last_flag;

    // per-lane precision slice (cols 4l..4l+3)
    const float4 pc = ((const float4*)prec)[l];

    // ---- prologue: stage W = prec*mu as fp16 at offset 0 (256 x 272), adj[k] ----
    {
        const float4* mr = (const float4*)(mu + (long)(w * 32) * DDIM);
        #pragma unroll 4
        for (int i = 0; i < 32; i++) {
            const int krow = w * 32 + i;
            float4 f = mr[i * 32 + l];
            float wx = pc.x * f.x, wy = pc.y * f.y, wz = pc.z * f.z, ww = pc.w * f.w;
            float s = wx * f.x;
            s = fmaf(wy, f.y, s);
            s = fmaf(wz, f.z, s);
            s = fmaf(ww, f.w, s);
            #pragma unroll
            for (int o = 16; o; o >>= 1) s += __shfl_xor_sync(0xFFFFFFFFu, s, o);
            __half2 lo = __floats2half2_rn(wx, wy);
            __half2 hi = __floats2half2_rn(wz, ww);
            uint2 v;
            v.x = *(uint32_t*)&lo;
            v.y = *(uint32_t*)&hi;
            *(uint2*)(smem + krow * RSTRIDE + l * 8) = v;
            if (l == 0) adj_s[krow] = -0.5f * s * L2E;
        }
    }
    __syncthreads();

    // ---- register-resident B fragments: warp w owns cols [32w, 32w+32) ----
    uint32_t B[8][2][4];   // 64 regs
    #pragma unroll
    for (int ks = 0; ks < 8; ks++) {
        #pragma unroll
        for (int tp = 0; tp < 2; tp++) {
            uint32_t addr = sb
                + (w * 32 + tp * 16 + ((m >> 1) << 3) + r) * RSTRIDE
                + ((ks << 4) + ((m & 1) << 3)) * 2;
            ldm_x4(addr, B[ks][tp][0], B[ks][tp][1], B[ks][tp][2], B[ks][tp][3]);
        }
    }
    // adj (+CSHIFT) for this lane's 8 columns, fp32
    float av[8];
    #pragma unroll
    for (int t = 0; t < 4; t++) {
        const int col = w * 32 + 8 * t + 2 * (l & 3);
        av[2 * t]     = adj_s[col]     + CSHIFT;
        av[2 * t + 1] = adj_s[col + 1] + CSHIFT;
    }
    __syncthreads();   // W region dead; x double-buffer lives at SBUF

    float acc_thr = 0.f;
    float xsq_acc = 0.f;

    // ---- stage first tile into buf0: warp w loads rows w*16..w*16+15 ----
    {
        const int tile0 = blockIdx.x;
        const float4* xr = (const float4*)(x + (long)(tile0 * MT + w * 16) * DDIM);
        #pragma unroll 8
        for (int i = 0; i < 16; i++) {
            float4 f = xr[i * 32 + l];
            xsq_acc = fmaf(pc.x * f.x, f.x, xsq_acc);
            xsq_acc = fmaf(pc.y * f.y, f.y, xsq_acc);
            xsq_acc = fmaf(pc.z * f.z, f.z, xsq_acc);
            xsq_acc = fmaf(pc.w * f.w, f.w, xsq_acc);
            __half2 lo = __floats2half2_rn(f.x, f.y);
            __half2 hi = __floats2half2_rn(f.z, f.w);
            uint2 v;
            v.x = *(uint32_t*)&lo;
            v.y = *(uint32_t*)&hi;
            *(uint2*)(smem + SBUF + (w * 16 + i) * RSTRIDE + l * 8) = v;
        }
    }
    __syncthreads();

    int par = 0;
    for (int tile = blockIdx.x; tile < NTILES; tile += gridDim.x, par ^= 1) {
        const uint32_t cur = sb + SBUF + par * BUFSZ;
        const int nxt = tile + gridDim.x;
        const bool do_stage = (nxt < NTILES);
        const float4* xr = (const float4*)(x + (long)(nxt * MT + w * 16) * DDIM);
        const uint32_t nbuf = sb + SBUF + (par ^ 1) * BUFSZ;

        // ---- compute with staging interleaved: per mt, stage 2 rows of NEXT tile ----
        #pragma unroll 1
        for (int mt = 0; mt < 8; mt++) {
            // stage rows 2*mt, 2*mt+1 of next tile (write-only to other buffer)
            if (do_stage) {
                #pragma unroll
                for (int ii = 0; ii < 2; ii++) {
                    const int i = 2 * mt + ii;
                    float4 f = xr[i * 32 + l];
                    xsq_acc = fmaf(pc.x * f.x, f.x, xsq_acc);
                    xsq_acc = fmaf(pc.y * f.y, f.y, xsq_acc);
                    xsq_acc = fmaf(pc.z * f.z, f.z, xsq_acc);
                    xsq_acc = fmaf(pc.w * f.w, f.w, xsq_acc);
                    __half2 lo = __floats2half2_rn(f.x, f.y);
                    __half2 hi = __floats2half2_rn(f.z, f.w);
                    uint2 v;
                    v.x = *(uint32_t*)&lo;
                    v.y = *(uint32_t*)&hi;
                    *(uint2*)((char*)smem + (nbuf - sb) + (w * 16 + i) * RSTRIDE + l * 8) = v;
                }
            }

            uint32_t acc[4][2] = {};   // half2 accumulators
            uint32_t a0[4], a1[4];
            const uint32_t rowad = cur + (mt * 16 + ((m & 1) << 3) + r) * RSTRIDE
                                 + (((m >> 1) << 3)) * 2;
            ldm_x4(rowad, a0[0], a0[1], a0[2], a0[3]);
            #pragma unroll
            for (int ks = 0; ks < 8; ks++) {
                uint32_t* ac = (ks & 1) ? a1 : a0;
                uint32_t* an = (ks & 1) ? a0 : a1;
                if (ks < 7)
                    ldm_x4(rowad + ((ks + 1) << 5), an[0], an[1], an[2], an[3]);
                #pragma unroll
                for (int t = 0; t < 4; t++)
                    mma16816_h(acc[t], ac, &B[ks][t >> 1][(t & 1) * 2]);
            }
            // per-lane 8-col partial sum of exp2(v): unpack half2 -> fp32, no max
            #pragma unroll
            for (int sub = 0; sub < 2; sub++) {
                float2 f0 = __half22float2(*(__half2*)&acc[0][sub]);
                float2 f1 = __half22float2(*(__half2*)&acc[1][sub]);
                float2 f2 = __half22float2(*(__half2*)&acc[2][sub]);
                float2 f3 = __half22float2(*(__half2*)&acc[3][sub]);
                float s01 = ex2f(fmaf(f0.x, L2E, av[0])) + ex2f(fmaf(f0.y, L2E, av[1]));
                float s23 = ex2f(fmaf(f1.x, L2E, av[2])) + ex2f(fmaf(f1.y, L2E, av[3]));
                float s45 = ex2f(fmaf(f2.x, L2E, av[4])) + ex2f(fmaf(f2.y, L2E, av[5]));
                float s67 = ex2f(fmaf(f3.x, L2E, av[6])) + ex2f(fmaf(f3.y, L2E, av[7]));
                const float s = (s01 + s23) + (s45 + s67);
                const int row = mt * 16 + sub * 8 + (l >> 2);
                // slot = w*4 + (l&3); stride 36 floats -> conflict-free
                ((float*)(smem + SPART))[row * 36 + w * 4 + (l & 3)] = s;
            }
        }
        __syncthreads();   // partials ready AND next-tile buffer fully staged

        // ---- merge: pure deterministic fp32 sum of 32 partials + one lg2 per row ----
        if (tid < MT) {
            const float4* pr = (const float4*)(smem + SPART + tid * 144);
            float s = 0.f;
            #pragma unroll
            for (int j = 0; j < 8; j++) {
                float4 f = pr[j];
                s += ((f.x + f.y) + (f.z + f.w));
            }
            acc_thr += LN2 * (lg2f(s) - CSHIFT);
        }
        __syncthreads();
    }

    // fold thread-local xsq (additive pass-through of logsumexp)
    acc_thr -= 0.5f * xsq_acc;

    // ---- deterministic block reduction ----
    float a = acc_thr;
    #pragma unroll
    for (int o = 16; o; o >>= 1) a += __shfl_xor_sync(0xFFFFFFFFu, a, o);
    if (l == 0) red_s[w] = a;
    __syncthreads();
    if (tid == 0) {
        float t = 0.f;
        #pragma unroll
        for (int i = 0; i < 8; i++) t += red_s[i];
        g_partials[blockIdx.x] = t;
        __threadfence();
        unsigned int c = atomicAdd(&g_count, 1u);
        last_flag = (c == (unsigned)(gridDim.x - 1)) ? 1u : 0u;
    }
    __syncthreads();

    // ---- last CTA: deterministic final reduction (fixed lane->index map) ----
    if (last_flag && w == 0) {
        float s = 0.f;
        #pragma unroll
        for (int i = l; i < NCTAS; i += 32) s += __ldcg(&g_partials[i]);
        #pragma unroll
        for (int o = 16; o; o >>= 1) s += __shfl_xor_sync(0xFFFFFFFFu, s, o);
        if (l == 0) {
            out[0] = -s;
            g_count = 0;          // reset for next graph replay
            __threadfence();
        }
    }
}

extern "C" void kernel_launch(void* const* d_in, const int* in_sizes, int n_in,
                              void* d_out, int out_size) {
    const float* x    = (const float*)d_in[0];
    const float* mu   = (const float*)d_in[1];
    const float* prec = (const float*)d_in[2];
    float* out = (float*)d_out;

    cudaFuncSetAttribute(gmm_lse_kernel, cudaFuncAttributeMaxDynamicSharedMemorySize, SMEM_TOTAL);
    gmm_lse_kernel<<<NCTAS, THREADS, SMEM_TOTAL>>>(x, mu, prec, out);
}